// round 17
// baseline (speedup 1.0000x reference)
#include <cuda_runtime.h>
#include <cuda_bf16.h>
#include <cstdint>

#define N_BANDS    128
#define RESO       64
#define N_FRAMES   128
#define N_SAMPLES  32768
#define BATCH      16
#define N_ROWS     (BATCH * N_BANDS)

typedef unsigned long long u64;

// Pair table: g_framep[i*2048 + c*16 + b] = (frames[b,c,i], frames[b,c,min(i+1,127)])
__device__ __align__(16) float2 g_framep[N_FRAMES * N_ROWS];

__device__ __forceinline__ u64 fma2(u64 a, u64 b, u64 c) {
    u64 d;
    asm("fma.rn.f32x2 %0, %1, %2, %3;" : "=l"(d) : "l"(a), "l"(b), "l"(c));
    return d;
}
__device__ __forceinline__ u64 dup32(float x) {
    u64 r;
    unsigned int xi = __float_as_uint(x);
    asm("mov.b64 %0, {%1, %1};" : "=l"(r) : "r"(xi));
    return r;
}
__device__ __forceinline__ float u64lo(u64 v) {
    return __uint_as_float((unsigned int)(v & 0xFFFFFFFFull));
}
__device__ __forceinline__ float u64hi(u64 v) {
    return __uint_as_float((unsigned int)(v >> 32));
}

// ---------------------------------------------------------------------------
// Kernel 1: 128 blocks (band c) x 512 threads (R15 version, proven).
// ---------------------------------------------------------------------------
__global__ __launch_bounds__(512)
void frames_kernel(const float* __restrict__ x,
                   const float* __restrict__ reso) {
    __shared__ float resT[N_FRAMES * 66];
    __shared__ float xs[1024];
    __shared__ float ps[16 * 66];
    __shared__ float scratch[2048];

    const int tid = threadIdx.x;
    const int c = blockIdx.x;

    for (int idx = tid; idx < RESO * N_FRAMES; idx += 512) {
        const int r = idx >> 7;
        const int f = idx & 127;
        resT[f * 66 + r] = reso[idx];
    }
    for (int idx = tid; idx < 16 * RESO; idx += 512) {
        const int b = idx >> 6;
        const int r = idx & 63;
        xs[idx] = x[(b * 128 + c) * RESO + r];
    }
    __syncthreads();

    {
        const int w = tid >> 5;
        const int lane = tid & 31;
        if (w < 16) {
            float v0 = xs[w * 64 + lane];
            float v1 = xs[w * 64 + lane + 32];
            float m = fmaxf(v0, v1);
            #pragma unroll
            for (int off = 16; off > 0; off >>= 1)
                m = fmaxf(m, __shfl_xor_sync(0xFFFFFFFFu, m, off));
            float e0 = __expf(v0 - m);
            float e1 = __expf(v1 - m);
            float s = e0 + e1;
            #pragma unroll
            for (int off = 16; off > 0; off >>= 1)
                s += __shfl_xor_sync(0xFFFFFFFFu, s, off);
            float inv = 1.0f / s;
            ps[w * 66 + lane]      = e0 * inv;
            ps[w * 66 + lane + 32] = e1 * inv;
        }
    }
    __syncthreads();

    const int b  = tid & 15;
    const int f0 = (tid >> 4) & 15;
    const int rh = tid >> 8;
    const int t256 = tid & 255;

    float v[8];
    {
        u64 acc2[8];
        #pragma unroll
        for (int i = 0; i < 8; ++i) acc2[i] = 0ull;
        const int rrbase = rh * 16;
        #pragma unroll 4
        for (int rr = 0; rr < 16; ++rr) {
            const u64 psp = *reinterpret_cast<const u64*>(
                &ps[b * 66 + 2 * (rrbase + rr)]);
            #pragma unroll
            for (int i = 0; i < 8; ++i) {
                const u64 rp = *reinterpret_cast<const u64*>(
                    &resT[(f0 + 16 * i) * 66 + 2 * (rrbase + rr)]);
                acc2[i] = fma2(rp, psp, acc2[i]);
            }
        }
        #pragma unroll
        for (int i = 0; i < 8; ++i) v[i] = u64lo(acc2[i]) + u64hi(acc2[i]);
    }

    if (rh == 1) {
        #pragma unroll
        for (int i = 0; i < 8; ++i) scratch[i * 256 + t256] = v[i];
    }
    __syncthreads();
    if (rh == 0) {
        #pragma unroll
        for (int i = 0; i < 8; ++i) v[i] += scratch[i * 256 + t256];
    }
    __syncthreads();

    float* fr = scratch;
    if (rh == 0) {
        #pragma unroll
        for (int i = 0; i < 8; ++i)
            fr[(f0 + 16 * i) * 16 + b] = v[i];
    }
    __syncthreads();

    if (rh == 0) {
        #pragma unroll
        for (int k = 0; k < 8; ++k) {
            const int p = f0 + 16 * k;
            const int pn = (p + 1 < N_FRAMES) ? p + 1 : N_FRAMES - 1;
            const float lo = fr[p * 16 + b];
            const float hi = fr[pn * 16 + b];
            g_framep[p * N_ROWS + c * 16 + b] = make_float2(lo, hi);
        }
    }

    __threadfence();
    asm volatile("griddepcontrol.launch_dependents;");
}

// ---------------------------------------------------------------------------
// Kernel 2 (PDL): 128 blocks x 512 threads, 96KB dynamic smem.
// Block n = samples [256n, 256n+256), ALL 128 bands -> fb rows are 1KB
// CONTIGUOUS DRAM reads (4x coarser than before). Double-buffered 32KB
// chunks (32 bands x 256 samples). Frame crossing at mid-tile handled by
// two pair tables: FPa (idx max(n-1,0)) for samples 0-127, FPb (idx n) for
// 128-255; selection is warp-uniform (st = bits 7-8 of tid).
// Thread: sg=tid&15 (4 samples), bq=(tid>>4)&7 (2 batches), st (64-sample
// subtile). Per band: 1 LDS.128 fb + 4 dup MOV + 1 LDS.128 FP + 8 fma2;
// 3 smem wavefronts/warp/band. Epilogue fully thread-local (no reduction).
// ---------------------------------------------------------------------------
__global__ __launch_bounds__(512, 1)
void mix_kernel(const float* __restrict__ fb,
                float* __restrict__ out) {
    extern __shared__ __align__(16) float SM[];
    // layout (floats): fbbuf[2][8192] | FPa[4096] | FPb[4096]  = 96KB

    const int tid = threadIdx.x;
    const int n = blockIdx.x;
    const int s_base = n * 256;

    const int ia = (n > 0) ? n - 1 : 0;   // pair idx, samples [0,128)
    const int ib = n;                     // pair idx, samples [128,256)

    const unsigned int fb_s0 = (unsigned int)__cvta_generic_to_shared(&SM[0]);
    const unsigned int FPa_s = (unsigned int)__cvta_generic_to_shared(&SM[16384]);
    const unsigned int FPb_s = (unsigned int)__cvta_generic_to_shared(&SM[20480]);
    const u64* FPa64 = reinterpret_cast<const u64*>(&SM[16384]);
    const u64* FPb64 = reinterpret_cast<const u64*>(&SM[20480]);

    // fb chunk = 32 bands x 256 samples = 32KB, rows of 1KB contiguous.
#define STAGE_FB(CHUNK, BUF)                                                  \
    {                                                                         \
        _Pragma("unroll")                                                     \
        for (int i = 0; i < 4; ++i) {                                         \
            const int o = (i * 512 + tid) * 16;                               \
            const int row = o >> 10;                                          \
            const int within = o & 1023;                                      \
            const float* g = fb + ((CHUNK) * 32 + row) * N_SAMPLES            \
                               + s_base + (within >> 2);                      \
            asm volatile("cp.async.cg.shared.global [%0], [%1], 16;\n"        \
                         :: "r"(fb_s0 + (BUF) * 32768 + o), "l"(g));          \
        }                                                                     \
        asm volatile("cp.async.commit_group;\n");                             \
    }

    // Pre-wait: chunks 0,1 (independent of frames).
    STAGE_FB(0, 0);
    STAGE_FB(1, 1);

    // Wait for frames, then stage both FP tables (16KB each, L2-hot).
    asm volatile("griddepcontrol.wait;" ::: "memory");
    {
        const char* ga = (const char*)(g_framep + ia * N_ROWS);
        const char* gb = (const char*)(g_framep + ib * N_ROWS);
        #pragma unroll
        for (int i = 0; i < 2; ++i) {
            const int o = (i * 512 + tid) * 16;
            asm volatile("cp.async.cg.shared.global [%0], [%1], 16;\n"
                         :: "r"(FPa_s + o), "l"(ga + o));
            asm volatile("cp.async.cg.shared.global [%0], [%1], 16;\n"
                         :: "r"(FPb_s + o), "l"(gb + o));
        }
        asm volatile("cp.async.commit_group;\n");
    }

    const int sg = tid & 15;             // 4-sample group within subtile
    const int bq = (tid >> 4) & 7;       // batch pair (batches 2bq, 2bq+1)
    const int st = tid >> 7;             // 64-sample subtile 0..3
    const u64* __restrict__ FPt = (st < 2) ? FPa64 : FPb64;   // warp-uniform

    u64 acc[8];   // acc[bp*4+j]: batch 2bq+bp, sample j; lanes (dot0, dot1)
    #pragma unroll
    for (int p = 0; p < 8; ++p) acc[p] = 0ull;

#define PROC(BUF, CH)                                                         \
    {                                                                         \
        _Pragma("unroll 4")                                                   \
        for (int cb = 0; cb < 32; ++cb) {                                     \
            const int c = (CH) * 32 + cb;                                     \
            const float4 fv = *reinterpret_cast<const float4*>(               \
                &SM[(BUF) * 8192 + cb * 256 + st * 64 + sg * 4]);             \
            const u64 d0 = dup32(fv.x);                                       \
            const u64 d1 = dup32(fv.y);                                       \
            const u64 d2 = dup32(fv.z);                                       \
            const u64 d3 = dup32(fv.w);                                       \
            const ulonglong2 fp2 = *reinterpret_cast<const ulonglong2*>(      \
                &FPt[c * 16 + bq * 2]);                                       \
            acc[0] = fma2(fp2.x, d0, acc[0]);                                 \
            acc[1] = fma2(fp2.x, d1, acc[1]);                                 \
            acc[2] = fma2(fp2.x, d2, acc[2]);                                 \
            acc[3] = fma2(fp2.x, d3, acc[3]);                                 \
            acc[4] = fma2(fp2.y, d0, acc[4]);                                 \
            acc[5] = fma2(fp2.y, d1, acc[5]);                                 \
            acc[6] = fma2(fp2.y, d2, acc[6]);                                 \
            acc[7] = fma2(fp2.y, d3, acc[7]);                                 \
        }                                                                     \
    }

#define WAITG(N) asm volatile("cp.async.wait_group %0;\n" :: "n"(N) : "memory")

    WAITG(0); __syncthreads();          // chunk0, chunk1, FP all resident
    PROC(0, 0);
    __syncthreads(); STAGE_FB(2, 0);    // buf0 free -> chunk2
    PROC(1, 1);
    __syncthreads(); STAGE_FB(3, 1);    // buf1 free -> chunk3
    WAITG(1); __syncthreads();          // chunk2 resident
    PROC(0, 2);
    WAITG(0); __syncthreads();          // chunk3 resident
    PROC(1, 3);

#undef STAGE_FB
#undef PROC
#undef WAITG

    // --- Epilogue: fully thread-local interp + store ---
    {
        const int s0 = s_base + st * 64 + sg * 4;
        float w[4];
        #pragma unroll
        for (int j = 0; j < 4; ++j) {
            float pos = (float)(s0 + j) * (1.0f / 256.0f)
                        + (0.5f / 256.0f - 0.5f);
            pos = fminf(fmaxf(pos, 0.0f), 127.0f);
            w[j] = pos - floorf(pos);
        }
        #pragma unroll
        for (int bp = 0; bp < 2; ++bp) {
            float4 o;
            float* ov = &o.x;
            #pragma unroll
            for (int j = 0; j < 4; ++j) {
                const u64 A = acc[bp * 4 + j];
                const float a0 = u64lo(A);
                const float a1 = u64hi(A);
                ov[j] = fmaf(w[j], a1 - a0, a0) * (1.0f / 128.0f);
            }
            *reinterpret_cast<float4*>(
                out + (bq * 2 + bp) * N_SAMPLES + s0) = o;
        }
    }
}

// ---------------------------------------------------------------------------
extern "C" void kernel_launch(void* const* d_in, const int* in_sizes, int n_in,
                              void* d_out, int out_size) {
    const float* x = nullptr;      // (16,128,64)    = 131072
    const float* reso = nullptr;   // (64,128)       = 8192
    const float* fb = nullptr;     // (1,128,32768)  = 4194304
    for (int i = 0; i < n_in; ++i) {
        if (in_sizes[i] == BATCH * N_BANDS * RESO)      x = (const float*)d_in[i];
        else if (in_sizes[i] == RESO * N_FRAMES)        reso = (const float*)d_in[i];
        else if (in_sizes[i] == N_BANDS * N_SAMPLES)    fb = (const float*)d_in[i];
    }
    float* out = (float*)d_out;

    static bool attr_set = false;
    if (!attr_set) {
        cudaFuncSetAttribute(mix_kernel,
                             cudaFuncAttributeMaxDynamicSharedMemorySize,
                             96 * 1024);
        attr_set = true;
    }

    frames_kernel<<<N_BANDS, 512>>>(x, reso);

    cudaLaunchConfig_t cfg = {};
    cfg.gridDim = dim3(N_SAMPLES / 256);
    cfg.blockDim = dim3(512);
    cfg.dynamicSmemBytes = 96 * 1024;
    cfg.stream = 0;
    cudaLaunchAttribute attrs[1];
    attrs[0].id = cudaLaunchAttributeProgrammaticStreamSerialization;
    attrs[0].val.programmaticStreamSerializationAllowed = 1;
    cfg.attrs = attrs;
    cfg.numAttrs = 1;
    cudaLaunchKernelEx(&cfg, mix_kernel, fb, out);
}